// round 4
// baseline (speedup 1.0000x reference)
#include <cuda_runtime.h>

#define FDIM 1024
#define CDIM 64
#define NROWS 65536
#define NTHREADS 256

// Scratch (no allocations allowed)
__device__ int    g_meta[FDIM];      // seg | (pos << 8)
__device__ int    g_start[CDIM + 1]; // group boundaries in sorted order
__device__ double g_acc[64];         // interleaved loss accumulators

// ---------------------------------------------------------------------------
// Setup: derive seg ids (argmax of one-hot rows), group-sorted permutation,
// group boundaries. Also zeroes the accumulators. <<<1, 1024>>>
// ---------------------------------------------------------------------------
__global__ void setup_kernel(const float* __restrict__ mask) {
    __shared__ int cnt[CDIM];
    __shared__ int base[CDIM + 1];
    int f = threadIdx.x;

    if (f < CDIM) cnt[f] = 0;
    __syncthreads();

    // argmax over the one-hot row
    int s = 0;
    float best = -1.0f;
#pragma unroll 8
    for (int c = 0; c < CDIM; c++) {
        float v = mask[f * CDIM + c];
        if (v > best) { best = v; s = c; }
    }
    int r = atomicAdd(&cnt[s], 1);  // rank within group (order irrelevant for max)
    __syncthreads();

    if (f == 0) {
        int acc = 0;
        for (int c = 0; c < CDIM; c++) { base[c] = acc; acc += cnt[c]; }
        base[CDIM] = acc;
    }
    __syncthreads();

    if (f <= CDIM) g_start[f] = base[f];
    int pos = base[s] + r;
    g_meta[f] = s | (pos << 8);
    if (f < 64) g_acc[f] = 0.0;
}

// ---------------------------------------------------------------------------
// Main: one block per (b, s) row. 256 threads, float4 per thread.
// ---------------------------------------------------------------------------
__global__ void __launch_bounds__(NTHREADS) mix_kernel(
    const float* __restrict__ logits,
    const int* __restrict__ labels)   // int32! (JAX x64 disabled downcasts int64)
{
    __shared__ float srow[FDIM];   // row values, group-sorted layout
    __shared__ float red_tot[8];
    __shared__ float red_ls[8];
    __shared__ float red_cs[2];
    __shared__ float s_gml;

    const int row  = blockIdx.x;
    const int t    = threadIdx.x;
    const int lane = t & 31;
    const int wid  = t >> 5;

    const int label = labels[row];

    float4 v = reinterpret_cast<const float4*>(logits + (size_t)row * FDIM)[t];
    int4  mt = reinterpret_cast<const int4*>(g_meta)[t];

    float total = 0.0f, lsum = 0.0f;

    {   // elem 0
        float e = __expf(v.x); total += e;
        if ((mt.x & 0xFF) == label) lsum += e;
        srow[(mt.x >> 8) & 1023] = v.x;
    }
    {   // elem 1
        float e = __expf(v.y); total += e;
        if ((mt.y & 0xFF) == label) lsum += e;
        srow[(mt.y >> 8) & 1023] = v.y;
    }
    {   // elem 2
        float e = __expf(v.z); total += e;
        if ((mt.z & 0xFF) == label) lsum += e;
        srow[(mt.z >> 8) & 1023] = v.z;
    }
    {   // elem 3
        float e = __expf(v.w); total += e;
        if ((mt.w & 0xFF) == label) lsum += e;
        srow[(mt.w >> 8) & 1023] = v.w;
    }

    // Block reduction of total / lsum (warp shuffle + smem)
#pragma unroll
    for (int o = 16; o; o >>= 1) {
        total += __shfl_xor_sync(0xFFFFFFFFu, total, o);
        lsum  += __shfl_xor_sync(0xFFFFFFFFu, lsum, o);
    }
    if (lane == 0) { red_tot[wid] = total; red_ls[wid] = lsum; }
    __syncthreads();   // also publishes the srow scatter

    // Segment max over contiguous sorted groups: thread c handles group c.
    if (t < CDIM) {
        int a = g_start[t], b = g_start[t + 1];
        float gm = -3.4e38f;
        int i = a;
        for (; i + 1 < b; i += 2) {
            float x0 = srow[i], x1 = srow[i + 1];
            gm = fmaxf(gm, fmaxf(x0, x1));
        }
        if (i < b) gm = fmaxf(gm, srow[i]);
        if (t == label) s_gml = gm;
        float eg = __expf(gm);
#pragma unroll
        for (int o = 16; o; o >>= 1)
            eg += __shfl_xor_sync(0xFFFFFFFFu, eg, o);
        if (lane == 0) red_cs[wid] = eg;
    }
    __syncthreads();

    if (t == 0) {
        float tt = 0.0f, ll = 0.0f;
#pragma unroll
        for (int i = 0; i < 8; i++) { tt += red_tot[i]; ll += red_ls[i]; }
        float csum = red_cs[0] + red_cs[1];
        float ce   = logf(csum) - s_gml;      // lse(coarse_max) - gmax[label]
        float nll  = logf(tt) - logf(ll);     // log(total) - log(group_sum[label])
        atomicAdd(&g_acc[row & 63], (double)(0.5f * (ce + nll)));
    }
}

// ---------------------------------------------------------------------------
// Finalize: mean over rows -> d_out[0]
// ---------------------------------------------------------------------------
__global__ void finalize_kernel(float* __restrict__ out) {
    double s = 0.0;
#pragma unroll
    for (int i = 0; i < 64; i++) s += g_acc[i];
    out[0] = (float)(s / (double)NROWS);
}

extern "C" void kernel_launch(void* const* d_in, const int* in_sizes, int n_in,
                              void* d_out, int out_size) {
    const float* logits = (const float*)d_in[0];  // [32, 2048, 1024] f32
    const int*   labels = (const int*)d_in[1];    // [32, 2048] i32 (x64 disabled)
    const float* mask   = (const float*)d_in[2];  // [1024, 64] f32

    setup_kernel<<<1, FDIM>>>(mask);
    mix_kernel<<<NROWS, NTHREADS>>>(logits, labels);
    finalize_kernel<<<1, 1>>>((float*)d_out);
}

// round 5
// speedup vs baseline: 1.4155x; 1.4155x over previous
#include <cuda_runtime.h>

#define FDIM 1024
#define CDIM 64
#define NROWS 65536
#define NTHREADS 256

// Scratch (no allocations allowed)
__device__ int    g_meta[FDIM];      // seg | (pos << 8)
__device__ int    g_start[CDIM + 1]; // group boundaries in sorted order
__device__ double g_acc[64];         // interleaved loss accumulators

// ---------------------------------------------------------------------------
// Setup: seg[f] = one-hot dot product with column indices (no branchy argmax),
// group-sorted permutation + boundaries. <<<1, 1024>>>
// ---------------------------------------------------------------------------
__global__ void setup_kernel(const float* __restrict__ mask) {
    __shared__ int cnt[CDIM];
    __shared__ int base[CDIM + 1];
    int f = threadIdx.x;

    if (f < CDIM) cnt[f] = 0;
    __syncthreads();

    // one-hot row: seg = sum_c c * mask[f][c]  (16 independent float4 loads)
    const float4* mrow = reinterpret_cast<const float4*>(mask + f * CDIM);
    float acc = 0.0f;
#pragma unroll
    for (int q = 0; q < 16; q++) {
        float4 m = mrow[q];
        float c0 = (float)(4 * q);
        acc = fmaf(m.x, c0,        acc);
        acc = fmaf(m.y, c0 + 1.0f, acc);
        acc = fmaf(m.z, c0 + 2.0f, acc);
        acc = fmaf(m.w, c0 + 3.0f, acc);
    }
    int s = (int)(acc + 0.5f);

    int r = atomicAdd(&cnt[s], 1);  // rank within group (order irrelevant for max)
    __syncthreads();

    if (f == 0) {
        int a = 0;
        for (int c = 0; c < CDIM; c++) { base[c] = a; a += cnt[c]; }
        base[CDIM] = a;
    }
    __syncthreads();

    if (f <= CDIM) g_start[f] = base[f];
    int pos = base[s] + r;
    g_meta[f] = s | (pos << 8);
    if (f < 64) g_acc[f] = 0.0;
}

// ---------------------------------------------------------------------------
// Main: one block per TWO rows. 256 threads, one float4 per thread per row
// (two independent loads in flight -> MLP 2). Segment scan uses 128 threads.
// ---------------------------------------------------------------------------
__global__ void __launch_bounds__(NTHREADS) mix_kernel(
    const float* __restrict__ logits,
    const int* __restrict__ labels)
{
    __shared__ float srow0[FDIM];
    __shared__ float srow1[FDIM];
    __shared__ float red_t0[8], red_t1[8];
    __shared__ float red_l0[8], red_l1[8];
    __shared__ float red_cs[4];     // warps 0,1 = row0 ; warps 2,3 = row1
    __shared__ float s_gml[2];

    const int row0 = blockIdx.x * 2;
    const int t    = threadIdx.x;
    const int lane = t & 31;
    const int wid  = t >> 5;

    const int label0 = labels[row0];
    const int label1 = labels[row0 + 1];

    // two independent streaming loads
    float4 v0 = reinterpret_cast<const float4*>(logits + (size_t)row0 * FDIM)[t];
    float4 v1 = reinterpret_cast<const float4*>(logits + (size_t)(row0 + 1) * FDIM)[t];
    int4  mt  = reinterpret_cast<const int4*>(g_meta)[t];

    const int s0 = mt.x & 0xFF, p0 = (mt.x >> 8) & 1023;
    const int s1 = mt.y & 0xFF, p1 = (mt.y >> 8) & 1023;
    const int s2 = mt.z & 0xFF, p2 = (mt.z >> 8) & 1023;
    const int s3 = mt.w & 0xFF, p3 = (mt.w >> 8) & 1023;

    float tot0 = 0.0f, ls0 = 0.0f, tot1 = 0.0f, ls1 = 0.0f;

    // row 0
    { float e = __expf(v0.x); tot0 += e; if (s0 == label0) ls0 += e; srow0[p0] = v0.x; }
    { float e = __expf(v0.y); tot0 += e; if (s1 == label0) ls0 += e; srow0[p1] = v0.y; }
    { float e = __expf(v0.z); tot0 += e; if (s2 == label0) ls0 += e; srow0[p2] = v0.z; }
    { float e = __expf(v0.w); tot0 += e; if (s3 == label0) ls0 += e; srow0[p3] = v0.w; }
    // row 1
    { float e = __expf(v1.x); tot1 += e; if (s0 == label1) ls1 += e; srow1[p0] = v1.x; }
    { float e = __expf(v1.y); tot1 += e; if (s1 == label1) ls1 += e; srow1[p1] = v1.y; }
    { float e = __expf(v1.z); tot1 += e; if (s2 == label1) ls1 += e; srow1[p2] = v1.z; }
    { float e = __expf(v1.w); tot1 += e; if (s3 == label1) ls1 += e; srow1[p3] = v1.w; }

#pragma unroll
    for (int o = 16; o; o >>= 1) {
        tot0 += __shfl_xor_sync(0xFFFFFFFFu, tot0, o);
        ls0  += __shfl_xor_sync(0xFFFFFFFFu, ls0, o);
        tot1 += __shfl_xor_sync(0xFFFFFFFFu, tot1, o);
        ls1  += __shfl_xor_sync(0xFFFFFFFFu, ls1, o);
    }
    if (lane == 0) { red_t0[wid] = tot0; red_l0[wid] = ls0;
                     red_t1[wid] = tot1; red_l1[wid] = ls1; }
    __syncthreads();   // publishes scatters + partial sums

    // Segment max: threads 0..63 -> row0 groups, 64..127 -> row1 groups.
    if (t < 2 * CDIM) {
        const int   c    = t & 63;
        const float* sr  = (t < CDIM) ? srow0 : srow1;
        const int   lab  = (t < CDIM) ? label0 : label1;
        int a = g_start[c], b = g_start[c + 1];
        float gm = -3.4e38f;
        int i = a;
        for (; i + 1 < b; i += 2)
            gm = fmaxf(gm, fmaxf(sr[i], sr[i + 1]));
        if (i < b) gm = fmaxf(gm, sr[i]);
        if (c == lab) s_gml[t >> 6] = gm;
        float eg = __expf(gm);
#pragma unroll
        for (int o = 16; o; o >>= 1)
            eg += __shfl_xor_sync(0xFFFFFFFFu, eg, o);
        if (lane == 0) red_cs[wid] = eg;
    }
    __syncthreads();

    if (t == 0) {
        float tt0 = 0.0f, ll0 = 0.0f, tt1 = 0.0f, ll1 = 0.0f;
#pragma unroll
        for (int i = 0; i < 8; i++) {
            tt0 += red_t0[i]; ll0 += red_l0[i];
            tt1 += red_t1[i]; ll1 += red_l1[i];
        }
        float ce0  = logf(red_cs[0] + red_cs[1]) - s_gml[0];
        float nll0 = logf(tt0) - logf(ll0);
        float ce1  = logf(red_cs[2] + red_cs[3]) - s_gml[1];
        float nll1 = logf(tt1) - logf(ll1);
        atomicAdd(&g_acc[blockIdx.x & 63],
                  (double)(0.5f * (ce0 + nll0)) + (double)(0.5f * (ce1 + nll1)));
    }
}

// ---------------------------------------------------------------------------
// Finalize: mean over rows -> d_out[0]
// ---------------------------------------------------------------------------
__global__ void finalize_kernel(float* __restrict__ out) {
    double s = 0.0;
#pragma unroll
    for (int i = 0; i < 64; i++) s += g_acc[i];
    out[0] = (float)(s / (double)NROWS);
}

extern "C" void kernel_launch(void* const* d_in, const int* in_sizes, int n_in,
                              void* d_out, int out_size) {
    const float* logits = (const float*)d_in[0];  // [32, 2048, 1024] f32
    const int*   labels = (const int*)d_in[1];    // [32, 2048] i32
    const float* mask   = (const float*)d_in[2];  // [1024, 64] f32

    setup_kernel<<<1, FDIM>>>(mask);
    mix_kernel<<<NROWS / 2, NTHREADS>>>(logits, labels);
    finalize_kernel<<<1, 1>>>((float*)d_out);
}

// round 6
// speedup vs baseline: 1.4498x; 1.0243x over previous
#include <cuda_runtime.h>

#define FDIM 1024
#define CDIM 64
#define NROWS 65536
#define NTHREADS 256
#define RPB 4                    // rows per block
#define NBLOCKS (NROWS / RPB)

// Scratch (no allocations allowed)
__device__ int    g_meta[FDIM];      // seg | (pos << 8)
__device__ int    g_start[CDIM + 1]; // group boundaries in sorted order
__device__ double g_acc[64];         // interleaved loss accumulators

// ---------------------------------------------------------------------------
// Setup: seg[f] via one-hot dot product; group ranks via smem atomics;
// group bases via 2-warp shuffle prefix scan (no serial loop). <<<1, 1024>>>
// ---------------------------------------------------------------------------
__global__ void setup_kernel(const float* __restrict__ mask) {
    __shared__ int cnt[CDIM];
    __shared__ int sbase[CDIM];
    __shared__ int s_w0sum;
    int f = threadIdx.x;
    int lane = f & 31;

    if (f < CDIM) cnt[f] = 0;
    __syncthreads();

    // one-hot row: seg = sum_c c * mask[f][c]  (16 independent float4 loads)
    const float4* mrow = reinterpret_cast<const float4*>(mask + f * CDIM);
    float acc = 0.0f;
#pragma unroll
    for (int q = 0; q < 16; q++) {
        float4 m = mrow[q];
        float c0 = (float)(4 * q);
        acc = fmaf(m.x, c0,        acc);
        acc = fmaf(m.y, c0 + 1.0f, acc);
        acc = fmaf(m.z, c0 + 2.0f, acc);
        acc = fmaf(m.w, c0 + 3.0f, acc);
    }
    int s = (int)(acc + 0.5f);

    int r = atomicAdd(&cnt[s], 1);  // rank within group (order irrelevant for max)
    __syncthreads();

    // exclusive prefix over cnt[0..63] with 2 warps
    int v = 0, sc = 0;
    if (f < CDIM) {
        v = cnt[f];
        sc = v;
#pragma unroll
        for (int o = 1; o < 32; o <<= 1) {
            int n = __shfl_up_sync(0xFFFFFFFFu, sc, o);
            if (lane >= o) sc += n;
        }
        if (f == 31) s_w0sum = sc;
    }
    __syncthreads();
    if (f < CDIM) {
        int base = sc - v + ((f >= 32) ? s_w0sum : 0);
        sbase[f] = base;
        g_start[f] = base;
        if (f == 0) g_start[CDIM] = FDIM;
        g_acc[f] = 0.0;
    }
    __syncthreads();

    int pos = sbase[s] + r;
    g_meta[f] = s | (pos << 8);
}

// ---------------------------------------------------------------------------
// Main: one block per FOUR rows. 256 threads; 4 independent float4 loads per
// thread (MLP 4). Segment scan uses all 256 threads (4 rows x 64 groups).
// ---------------------------------------------------------------------------
__global__ void __launch_bounds__(NTHREADS) mix_kernel(
    const float* __restrict__ logits,
    const int* __restrict__ labels)
{
    __shared__ float srow[RPB][FDIM];
    __shared__ float red_t[RPB][8];
    __shared__ float red_l[RPB][8];
    __shared__ float red_cs[8];      // 2 warps per row, 4 rows
    __shared__ float s_gml[RPB];
    __shared__ int   s_lab[RPB];

    const int row0 = blockIdx.x * RPB;
    const int t    = threadIdx.x;
    const int lane = t & 31;
    const int wid  = t >> 5;

    if (t < RPB) s_lab[t] = labels[row0 + t];

    // 4 independent streaming loads (front-batched by ptxas)
    const float4* lp = reinterpret_cast<const float4*>(logits + (size_t)row0 * FDIM);
    float4 v0 = lp[t];
    float4 v1 = lp[256 + t];
    float4 v2 = lp[512 + t];
    float4 v3 = lp[768 + t];
    int4  mt  = reinterpret_cast<const int4*>(g_meta)[t];
    __syncthreads();   // publish s_lab

    const int sg0 = mt.x & 0xFF, p0 = (mt.x >> 8) & 1023;
    const int sg1 = mt.y & 0xFF, p1 = (mt.y >> 8) & 1023;
    const int sg2 = mt.z & 0xFF, p2 = (mt.z >> 8) & 1023;
    const int sg3 = mt.w & 0xFF, p3 = (mt.w >> 8) & 1023;
    const int l0 = s_lab[0], l1 = s_lab[1], l2 = s_lab[2], l3 = s_lab[3];

    float tot0 = 0.f, ls0 = 0.f, tot1 = 0.f, ls1 = 0.f;
    float tot2 = 0.f, ls2 = 0.f, tot3 = 0.f, ls3 = 0.f;

    { float e = __expf(v0.x); tot0 += e; if (sg0 == l0) ls0 += e; srow[0][p0] = v0.x; }
    { float e = __expf(v0.y); tot0 += e; if (sg1 == l0) ls0 += e; srow[0][p1] = v0.y; }
    { float e = __expf(v0.z); tot0 += e; if (sg2 == l0) ls0 += e; srow[0][p2] = v0.z; }
    { float e = __expf(v0.w); tot0 += e; if (sg3 == l0) ls0 += e; srow[0][p3] = v0.w; }

    { float e = __expf(v1.x); tot1 += e; if (sg0 == l1) ls1 += e; srow[1][p0] = v1.x; }
    { float e = __expf(v1.y); tot1 += e; if (sg1 == l1) ls1 += e; srow[1][p1] = v1.y; }
    { float e = __expf(v1.z); tot1 += e; if (sg2 == l1) ls1 += e; srow[1][p2] = v1.z; }
    { float e = __expf(v1.w); tot1 += e; if (sg3 == l1) ls1 += e; srow[1][p3] = v1.w; }

    { float e = __expf(v2.x); tot2 += e; if (sg0 == l2) ls2 += e; srow[2][p0] = v2.x; }
    { float e = __expf(v2.y); tot2 += e; if (sg1 == l2) ls2 += e; srow[2][p1] = v2.y; }
    { float e = __expf(v2.z); tot2 += e; if (sg2 == l2) ls2 += e; srow[2][p2] = v2.z; }
    { float e = __expf(v2.w); tot2 += e; if (sg3 == l2) ls2 += e; srow[2][p3] = v2.w; }

    { float e = __expf(v3.x); tot3 += e; if (sg0 == l3) ls3 += e; srow[3][p0] = v3.x; }
    { float e = __expf(v3.y); tot3 += e; if (sg1 == l3) ls3 += e; srow[3][p1] = v3.y; }
    { float e = __expf(v3.z); tot3 += e; if (sg2 == l3) ls3 += e; srow[3][p2] = v3.z; }
    { float e = __expf(v3.w); tot3 += e; if (sg3 == l3) ls3 += e; srow[3][p3] = v3.w; }

#pragma unroll
    for (int o = 16; o; o >>= 1) {
        tot0 += __shfl_xor_sync(0xFFFFFFFFu, tot0, o);
        ls0  += __shfl_xor_sync(0xFFFFFFFFu, ls0, o);
        tot1 += __shfl_xor_sync(0xFFFFFFFFu, tot1, o);
        ls1  += __shfl_xor_sync(0xFFFFFFFFu, ls1, o);
        tot2 += __shfl_xor_sync(0xFFFFFFFFu, tot2, o);
        ls2  += __shfl_xor_sync(0xFFFFFFFFu, ls2, o);
        tot3 += __shfl_xor_sync(0xFFFFFFFFu, tot3, o);
        ls3  += __shfl_xor_sync(0xFFFFFFFFu, ls3, o);
    }
    if (lane == 0) {
        red_t[0][wid] = tot0; red_l[0][wid] = ls0;
        red_t[1][wid] = tot1; red_l[1][wid] = ls1;
        red_t[2][wid] = tot2; red_l[2][wid] = ls2;
        red_t[3][wid] = tot3; red_l[3][wid] = ls3;
    }
    __syncthreads();   // publish scatters + partial sums

    // Segment max: all 256 threads. thread t -> row (t>>6), group (t&63).
    {
        const int j = t >> 6;
        const int c = t & 63;
        const float* sr = srow[j];
        int a = g_start[c], b = g_start[c + 1];
        float gm = -3.4e38f;
        int i = a;
        for (; i + 1 < b; i += 2)
            gm = fmaxf(gm, fmaxf(sr[i], sr[i + 1]));
        if (i < b) gm = fmaxf(gm, sr[i]);
        if (c == s_lab[j]) s_gml[j] = gm;
        float eg = __expf(gm);
#pragma unroll
        for (int o = 16; o; o >>= 1)
            eg += __shfl_xor_sync(0xFFFFFFFFu, eg, o);
        if (lane == 0) red_cs[wid] = eg;   // 2 entries per row
    }
    __syncthreads();

    if (t < RPB) {
        float tt = 0.f, ll = 0.f;
#pragma unroll
        for (int i = 0; i < 8; i++) { tt += red_t[t][i]; ll += red_l[t][i]; }
        float csum = red_cs[2 * t] + red_cs[2 * t + 1];
        float ce   = logf(csum) - s_gml[t];
        float nll  = logf(tt) - logf(ll);
        atomicAdd(&g_acc[(blockIdx.x * RPB + t) & 63],
                  (double)(0.5f * (ce + nll)));
    }
}

// ---------------------------------------------------------------------------
// Finalize: mean over rows -> d_out[0]
// ---------------------------------------------------------------------------
__global__ void finalize_kernel(float* __restrict__ out) {
    double s = 0.0;
#pragma unroll
    for (int i = 0; i < 64; i++) s += g_acc[i];
    out[0] = (float)(s / (double)NROWS);
}

extern "C" void kernel_launch(void* const* d_in, const int* in_sizes, int n_in,
                              void* d_out, int out_size) {
    const float* logits = (const float*)d_in[0];  // [32, 2048, 1024] f32
    const int*   labels = (const int*)d_in[1];    // [32, 2048] i32
    const float* mask   = (const float*)d_in[2];  // [1024, 64] f32

    setup_kernel<<<1, FDIM>>>(mask);
    mix_kernel<<<NBLOCKS, NTHREADS>>>(logits, labels);
    finalize_kernel<<<1, 1>>>((float*)d_out);
}

// round 7
// speedup vs baseline: 1.7152x; 1.1830x over previous
#include <cuda_runtime.h>

#define FDIM 1024
#define CDIM 64
#define NROWS 65536
#define RPB 8                    // rows (= warps) per block
#define NTHREADS (RPB * 32)
#define NBLOCKS (NROWS / RPB)

// Scratch (no allocations allowed)
__device__ int    g_meta[FDIM];      // seg | (pos << 8)
__device__ int    g_start[CDIM + 1]; // group boundaries in sorted order
__device__ double g_acc[64];         // interleaved loss accumulators

// ---------------------------------------------------------------------------
// Setup: seg[f] via one-hot dot product; group ranks via smem atomics;
// group bases via 2-warp shuffle prefix scan. <<<1, 1024>>>
// ---------------------------------------------------------------------------
__global__ void setup_kernel(const float* __restrict__ mask) {
    __shared__ int cnt[CDIM];
    __shared__ int sbase[CDIM];
    __shared__ int s_w0sum;
    int f = threadIdx.x;
    int lane = f & 31;

    if (f < CDIM) cnt[f] = 0;
    __syncthreads();

    const float4* mrow = reinterpret_cast<const float4*>(mask + f * CDIM);
    float acc = 0.0f;
#pragma unroll
    for (int q = 0; q < 16; q++) {
        float4 m = mrow[q];
        float c0 = (float)(4 * q);
        acc = fmaf(m.x, c0,        acc);
        acc = fmaf(m.y, c0 + 1.0f, acc);
        acc = fmaf(m.z, c0 + 2.0f, acc);
        acc = fmaf(m.w, c0 + 3.0f, acc);
    }
    int s = (int)(acc + 0.5f);

    int r = atomicAdd(&cnt[s], 1);
    __syncthreads();

    int v = 0, sc = 0;
    if (f < CDIM) {
        v = cnt[f];
        sc = v;
#pragma unroll
        for (int o = 1; o < 32; o <<= 1) {
            int n = __shfl_up_sync(0xFFFFFFFFu, sc, o);
            if (lane >= o) sc += n;
        }
        if (f == 31) s_w0sum = sc;
    }
    __syncthreads();
    if (f < CDIM) {
        int base = sc - v + ((f >= 32) ? s_w0sum : 0);
        sbase[f] = base;
        g_start[f] = base;
        if (f == 0) g_start[CDIM] = FDIM;
        g_acc[f] = 0.0;
    }
    __syncthreads();

    int pos = sbase[s] + r;
    g_meta[f] = s | (pos << 8);
}

// ---------------------------------------------------------------------------
// Main: warp-per-row, barrier-free after the one-time meta copy.
// Each lane: 8 batched float4 loads, exp + predicated label-sum + scatter to
// this warp's group-sorted smem slice, __syncwarp, then a vectorized
// (float4) masked scan of 2 contiguous groups, warp-shuffle finish.
// ---------------------------------------------------------------------------
__global__ void __launch_bounds__(NTHREADS, 5) mix_kernel(
    const float* __restrict__ logits,
    const int* __restrict__ labels)
{
    __shared__ float srow[RPB][FDIM];   // 32 KB: group-sorted values per warp
    __shared__ uint4 smeta[FDIM / 4];   // 4 KB: packed meta
    __shared__ int   sstart[CDIM + 1];

    const int t    = threadIdx.x;
    const int lane = t & 31;
    const int w    = t >> 5;

    // One-time block prologue
    smeta[t] = reinterpret_cast<const uint4*>(g_meta)[t];
    if (t <= CDIM) sstart[t] = g_start[t];
    __syncthreads();

    const int row   = blockIdx.x * RPB + w;
    const int label = labels[row];

    // 8 independent coalesced float4 loads (MLP 8)
    const float4* rp = reinterpret_cast<const float4*>(logits + (size_t)row * FDIM);
    float4 v0 = rp[lane];
    float4 v1 = rp[lane + 32];
    float4 v2 = rp[lane + 64];
    float4 v3 = rp[lane + 96];
    float4 v4 = rp[lane + 128];
    float4 v5 = rp[lane + 160];
    float4 v6 = rp[lane + 192];
    float4 v7 = rp[lane + 224];

    float tot = 0.0f, ls = 0.0f;
    float* my = srow[w];

#define DO_CHUNK(VV, CI)                                                     \
    {                                                                        \
        uint4 m = smeta[lane + 32 * (CI)];                                   \
        { float e = __expf(VV.x); tot += e;                                  \
          if ((int)(m.x & 0xFFu) == label) ls += e;                          \
          my[(m.x >> 8) & 1023u] = VV.x; }                                   \
        { float e = __expf(VV.y); tot += e;                                  \
          if ((int)(m.y & 0xFFu) == label) ls += e;                          \
          my[(m.y >> 8) & 1023u] = VV.y; }                                   \
        { float e = __expf(VV.z); tot += e;                                  \
          if ((int)(m.z & 0xFFu) == label) ls += e;                          \
          my[(m.z >> 8) & 1023u] = VV.z; }                                   \
        { float e = __expf(VV.w); tot += e;                                  \
          if ((int)(m.w & 0xFFu) == label) ls += e;                          \
          my[(m.w >> 8) & 1023u] = VV.w; }                                   \
    }

    DO_CHUNK(v0, 0) DO_CHUNK(v1, 1) DO_CHUNK(v2, 2) DO_CHUNK(v3, 3)
    DO_CHUNK(v4, 4) DO_CHUNK(v5, 5) DO_CHUNK(v6, 6) DO_CHUNK(v7, 7)
#undef DO_CHUNK

    __syncwarp();   // warp-private smem slice now consistent

    // Vectorized segment max: lane handles groups (lane) and (lane+32).
    const float4* my4 = reinterpret_cast<const float4*>(my);
    float gm0 = -3.4e38f, gm1 = -3.4e38f;
    {
        int a = sstart[lane], b = sstart[lane + 1];
        for (int q = a >> 2, qe = (b - 1) >> 2; q <= qe; q++) {
            float4 c = my4[q];
            int base = 4 * q;
            gm0 = fmaxf(gm0, (base     >= a && base     < b) ? c.x : -3.4e38f);
            gm0 = fmaxf(gm0, (base + 1 >= a && base + 1 < b) ? c.y : -3.4e38f);
            gm0 = fmaxf(gm0, (base + 2 >= a && base + 2 < b) ? c.z : -3.4e38f);
            gm0 = fmaxf(gm0, (base + 3 >= a && base + 3 < b) ? c.w : -3.4e38f);
        }
    }
    {
        int a = sstart[lane + 32], b = sstart[lane + 33];
        for (int q = a >> 2, qe = (b - 1) >> 2; q <= qe; q++) {
            float4 c = my4[q];
            int base = 4 * q;
            gm1 = fmaxf(gm1, (base     >= a && base     < b) ? c.x : -3.4e38f);
            gm1 = fmaxf(gm1, (base + 1 >= a && base + 1 < b) ? c.y : -3.4e38f);
            gm1 = fmaxf(gm1, (base + 2 >= a && base + 2 < b) ? c.z : -3.4e38f);
            gm1 = fmaxf(gm1, (base + 3 >= a && base + 3 < b) ? c.w : -3.4e38f);
        }
    }

    // gmax of the label's group (label uniform per warp)
    float cand = (label < 32) ? gm0 : gm1;
    float gml  = __shfl_sync(0xFFFFFFFFu, cand, label & 31);

    float csum = __expf(gm0) + __expf(gm1);
#pragma unroll
    for (int o = 16; o; o >>= 1) {
        csum += __shfl_xor_sync(0xFFFFFFFFu, csum, o);
        tot  += __shfl_xor_sync(0xFFFFFFFFu, tot, o);
        ls   += __shfl_xor_sync(0xFFFFFFFFu, ls, o);
    }

    if (lane == 0) {
        float ce  = logf(csum) - gml;       // lse(coarse_max) - gmax[label]
        float nll = logf(tot) - logf(ls);   // log(total) - log(group_sum[label])
        atomicAdd(&g_acc[row & 63], (double)(0.5f * (ce + nll)));
    }
}

// ---------------------------------------------------------------------------
// Finalize: mean over rows -> d_out[0]
// ---------------------------------------------------------------------------
__global__ void finalize_kernel(float* __restrict__ out) {
    double s = 0.0;
#pragma unroll
    for (int i = 0; i < 64; i++) s += g_acc[i];
    out[0] = (float)(s / (double)NROWS);
}

extern "C" void kernel_launch(void* const* d_in, const int* in_sizes, int n_in,
                              void* d_out, int out_size) {
    const float* logits = (const float*)d_in[0];  // [32, 2048, 1024] f32
    const int*   labels = (const int*)d_in[1];    // [32, 2048] i32
    const float* mask   = (const float*)d_in[2];  // [1024, 64] f32

    setup_kernel<<<1, FDIM>>>(mask);
    mix_kernel<<<NBLOCKS, NTHREADS>>>(logits, labels);
    finalize_kernel<<<1, 1>>>((float*)d_out);
}